// round 11
// baseline (speedup 1.0000x reference)
#include <cuda_runtime.h>
#include <cstdint>

#define ND 4096
#define NE 64
#define NTOK 16384
#define TOK_CTA 64
#define NTHREADS 128
#define KC 64
#define NSTAGE (ND / KC)        // 64

// Precomputed W fragments: [s][g][n][j] -> uint4 {h01, h23, m01, m23}  (1 MB)
__device__ uint4 g_wprep[NSTAGE * 4 * NE * 4];

// round-to-nearest fp16 2-way split: h = hi + mid + q, |q| <= 2^-22|h|, unbiased.
__device__ __forceinline__ void cvt_split_pair(float h0, float h1,
                                               uint32_t& hi2, uint32_t& mid2) {
    asm("cvt.rn.f16x2.f32 %0, %1, %2;" : "=r"(hi2) : "f"(h1), "f"(h0));   // lo half = h0
    float f0, f1;
    asm("{.reg .f16 a, b;\n\t mov.b32 {a, b}, %2;\n\t"
        "cvt.f32.f16 %0, a;\n\t cvt.f32.f16 %1, b;}"
        : "=f"(f0), "=f"(f1) : "r"(hi2));
    float r0 = h0 - f0;
    float r1 = h1 - f1;
    asm("cvt.rn.f16x2.f32 %0, %1, %2;" : "=r"(mid2) : "f"(r1), "f"(r0));
}

#define MMA(c, a, b0_, b1_) \
    asm volatile("mma.sync.aligned.m16n8k16.row.col.f32.f16.f16.f32 " \
        "{%0,%1,%2,%3}, {%4,%5,%6,%7}, {%8,%9}, {%0,%1,%2,%3};" \
        : "+f"((c)[0]), "+f"((c)[1]), "+f"((c)[2]), "+f"((c)[3]) \
        : "r"((a)[0]), "r"((a)[1]), "r"((a)[2]), "r"((a)[3]), "r"(b0_), "r"(b1_))

// ---- kernel 1: one-shot W conversion into fragment layout ----
__global__ __launch_bounds__(256)
void wprep_kernel(const float* __restrict__ W)
{
    const int idx = blockIdx.x * 256 + threadIdx.x;    // 65536 total
    const int j = idx & 3;
    const int n = (idx >> 2) & 63;
    const int g = (idx >> 8) & 3;
    const int s = idx >> 10;
    const int col = s * KC + g * 16 + j * 4;
    float4 w = *(const float4*)(W + (size_t)n * ND + col);
    uint32_t h01, m01, h23, m23;
    cvt_split_pair(w.x, w.y, h01, m01);
    cvt_split_pair(w.z, w.w, h23, m23);
    g_wprep[idx] = make_uint4(h01, h23, m01, m23);
}

// ---- kernel 2: GEMM + top-2 + softmax (no smem, no barriers) ----
__global__ __launch_bounds__(NTHREADS, 3)
void topk_router_kernel(const float* __restrict__ hs,
                        float* __restrict__ out)
{
    const int tid  = threadIdx.x;
    const int lane = tid & 31;
    const int warp = tid >> 5;
    const int j    = lane & 3;     // k-slot selector
    const int qr   = lane >> 2;    // row / n selector
    const int tok0 = blockIdx.x * TOK_CTA;

    // A: permuted-K fragment loads; global col = s*64 + 16g + 4j + {0..3}
    const float* a0p = hs + (size_t)(tok0 + warp * 16 + qr) * ND + 4 * j;
    const float* a1p = a0p + 8 * ND;

    float acc[8][4];
#pragma unroll
    for (int t = 0; t < 8; t++)
#pragma unroll
        for (int c = 0; c < 4; c++) acc[t][c] = 0.f;

    // A prologue: (s0,g0) and (s0,g1)
    float4 cur0 = *(const float4*)(a0p);
    float4 cur1 = *(const float4*)(a1p);
    float4 nx0  = *(const float4*)(a0p + 16);
    float4 nx1  = *(const float4*)(a1p + 16);

    const uint4* wp0 = g_wprep + qr * 4 + j;

    for (int s = 0; s < NSTAGE; s++) {
#pragma unroll
        for (int g = 0; g < 4; g++) {
            // distance-2 A prefetch: (s, g+2) or (s+1, g-2)
            float4 p0, p1;
            bool havePf;
            int pfoff = 0;
            if (g < 2)                 { havePf = true; pfoff = s * KC + (g + 2) * 16; }
            else if (s + 1 < NSTAGE)   { havePf = true; pfoff = (s + 1) * KC + (g - 2) * 16; }
            else                       { havePf = false; }
            if (havePf) {
                p0 = *(const float4*)(a0p + pfoff);
                p1 = *(const float4*)(a1p + pfoff);
            }

            // B fragments straight from the precomputed table (L1-resident)
            const uint4* wp = wp0 + (size_t)(s * 4 + g) * 256;
            uint4 bf[8];
#pragma unroll
            for (int t = 0; t < 8; t++) bf[t] = wp[t * 32];

            uint32_t aH[4], aM[4];
            cvt_split_pair(cur0.x, cur0.y, aH[0], aM[0]);   // slot 2j,   row qr
            cvt_split_pair(cur1.x, cur1.y, aH[1], aM[1]);   // slot 2j,   row qr+8
            cvt_split_pair(cur0.z, cur0.w, aH[2], aM[2]);   // slot 2j+8, row qr
            cvt_split_pair(cur1.z, cur1.w, aH[3], aM[3]);   // slot 2j+8, row qr+8

#pragma unroll
            for (int t = 0; t < 8; t++) MMA(acc[t], aH, bf[t].x, bf[t].y);
#pragma unroll
            for (int t = 0; t < 8; t++) MMA(acc[t], aM, bf[t].x, bf[t].y);
#pragma unroll
            for (int t = 0; t < 8; t++) MMA(acc[t], aH, bf[t].z, bf[t].w);

            cur0 = nx0; cur1 = nx1;
            if (havePf) { nx0 = p0; nx1 = p1; }
        }
    }

    // ---- epilogue: per-row top-2 + softmax, register-only + shfl merge ----
#pragma unroll
    for (int half = 0; half < 2; half++) {
        float m1 = -3.4e38f, m2 = -3.4e38f;
        int i1 = 0, i2 = 0;
#pragma unroll
        for (int t = 0; t < 8; t++) {
#pragma unroll
            for (int c = 0; c < 2; c++) {
                float v = acc[t][half * 2 + c];
                int e = 8 * t + 2 * j + c;
                if (v > m1) { m2 = m1; i2 = i1; m1 = v; i1 = e; }
                else if (v > m2) { m2 = v; i2 = e; }
            }
        }
#pragma unroll
        for (int off = 1; off <= 2; off <<= 1) {
            float om1 = __shfl_xor_sync(0xffffffffu, m1, off);
            float om2 = __shfl_xor_sync(0xffffffffu, m2, off);
            int   oi1 = __shfl_xor_sync(0xffffffffu, i1, off);
            int   oi2 = __shfl_xor_sync(0xffffffffu, i2, off);
            if (om1 > m1) {
                float nm2 = (om2 > m1) ? om2 : m1;
                int   ni2 = (om2 > m1) ? oi2 : i1;
                m1 = om1; i1 = oi1; m2 = nm2; i2 = ni2;
            } else if (om1 > m2) {
                m2 = om1; i2 = oi1;
            }
        }
        if (j == 0) {
            int tok = tok0 + warp * 16 + qr + half * 8;
            float ex = __expf(m2 - m1);
            float s1 = 1.0f / (1.0f + ex);
            out[2 * tok]     = s1;
            out[2 * tok + 1] = ex * s1;
            out[2 * NTOK + 2 * tok]     = (float)i1;
            out[2 * NTOK + 2 * tok + 1] = (float)i2;
        }
    }
}

extern "C" void kernel_launch(void* const* d_in, const int* in_sizes, int n_in,
                              void* d_out, int out_size)
{
    const float* hs = (const float*)d_in[0];   // (4, 4096, 4096) fp32
    const float* W  = (const float*)d_in[1];   // (64, 4096) fp32
    float* out      = (float*)d_out;           // [scores 32768][indices 32768]
    (void)in_sizes; (void)n_in; (void)out_size;

    wprep_kernel<<<256, 256>>>(W);
    topk_router_kernel<<<NTOK / TOK_CTA, NTHREADS>>>(hs, out);
}

// round 12
// speedup vs baseline: 1.2039x; 1.2039x over previous
#include <cuda_runtime.h>
#include <cstdint>

#define ND 4096
#define NE 64
#define NTOK 16384
#define TOK_CTA 64
#define NTHREADS 128
#define KC 64
#define NSTAGE (ND / KC)        // 64

// Precomputed W fragments: [s][g][n][j] -> uint4 {h01, h23, m01, m23}  (1 MB)
__device__ uint4 g_wprep[NSTAGE * 4 * NE * 4];

// round-to-nearest fp16 2-way split: h = hi + mid + q, |q| <= 2^-22|h|, unbiased.
__device__ __forceinline__ void cvt_split_pair(float h0, float h1,
                                               uint32_t& hi2, uint32_t& mid2) {
    asm("cvt.rn.f16x2.f32 %0, %1, %2;" : "=r"(hi2) : "f"(h1), "f"(h0));   // lo half = h0
    float f0, f1;
    asm("{.reg .f16 a, b;\n\t mov.b32 {a, b}, %2;\n\t"
        "cvt.f32.f16 %0, a;\n\t cvt.f32.f16 %1, b;}"
        : "=f"(f0), "=f"(f1) : "r"(hi2));
    float r0 = h0 - f0;
    float r1 = h1 - f1;
    asm("cvt.rn.f16x2.f32 %0, %1, %2;" : "=r"(mid2) : "f"(r1), "f"(r0));
}

#define MMA(c, a, b0_, b1_) \
    asm volatile("mma.sync.aligned.m16n8k16.row.col.f32.f16.f16.f32 " \
        "{%0,%1,%2,%3}, {%4,%5,%6,%7}, {%8,%9}, {%0,%1,%2,%3};" \
        : "+f"((c)[0]), "+f"((c)[1]), "+f"((c)[2]), "+f"((c)[3]) \
        : "r"((a)[0]), "r"((a)[1]), "r"((a)[2]), "r"((a)[3]), "r"(b0_), "r"(b1_))

// ---- kernel 1: one-shot W conversion into fragment layout ----
__global__ __launch_bounds__(256)
void wprep_kernel(const float* __restrict__ W)
{
    const int idx = blockIdx.x * 256 + threadIdx.x;    // 65536 total
    const int j = idx & 3;
    const int n = (idx >> 2) & 63;
    const int g = (idx >> 8) & 3;
    const int s = idx >> 10;
    const int col = s * KC + g * 16 + j * 4;
    float4 w = *(const float4*)(W + (size_t)n * ND + col);
    uint32_t h01, m01, h23, m23;
    cvt_split_pair(w.x, w.y, h01, m01);
    cvt_split_pair(w.z, w.w, h23, m23);
    g_wprep[idx] = make_uint4(h01, h23, m01, m23);
}

// ---- kernel 2: GEMM + top-2 + softmax; prepped fragments staged via smem ----
__global__ __launch_bounds__(NTHREADS, 2)
void topk_router_kernel(const float* __restrict__ hs,
                        float* __restrict__ out)
{
    __shared__ __align__(16) uint4 sbuf[2][1024];   // 16 KB per stage slab

    const int tid  = threadIdx.x;
    const int lane = tid & 31;
    const int warp = tid >> 5;
    const int j    = lane & 3;     // k-slot selector
    const int qr   = lane >> 2;    // row / n selector
    const int tok0 = blockIdx.x * TOK_CTA;

    // A: permuted-K fragment loads; global col = s*64 + 16g + 4j + {0..3}
    const float* a0p = hs + (size_t)(tok0 + warp * 16 + qr) * ND + 4 * j;
    const float* a1p = a0p + 8 * ND;

    float acc[8][4];
#pragma unroll
    for (int t = 0; t < 8; t++)
#pragma unroll
        for (int c = 0; c < 4; c++) acc[t][c] = 0.f;

    uint4 wstage[8];

    // ---- prologue: stage 0 slab into sbuf[0] ----
#pragma unroll
    for (int p = 0; p < 8; p++) wstage[p] = g_wprep[tid + p * 128];
#pragma unroll
    for (int p = 0; p < 8; p++) sbuf[0][tid + p * 128] = wstage[p];

    // A prologue: (s0,g0) and (s0,g1)
    float4 cur0 = *(const float4*)(a0p);
    float4 cur1 = *(const float4*)(a1p);
    float4 nx0  = *(const float4*)(a0p + 16);
    float4 nx1  = *(const float4*)(a1p + 16);
    __syncthreads();

    for (int s = 0; s < NSTAGE; s++) {
        // prefetch next stage slab into registers (coalesced, 4 wf per LDG.128)
        if (s + 1 < NSTAGE) {
            const uint4* src = g_wprep + (s + 1) * 1024;
#pragma unroll
            for (int p = 0; p < 8; p++) wstage[p] = src[tid + p * 128];
        }

        const uint4* buf = sbuf[s & 1];

#pragma unroll
        for (int g = 0; g < 4; g++) {
            // distance-2 A prefetch: (s, g+2) or (s+1, g-2)
            float4 p0, p1;
            bool havePf;
            int pfoff = 0;
            if (g < 2)                 { havePf = true; pfoff = s * KC + (g + 2) * 16; }
            else if (s + 1 < NSTAGE)   { havePf = true; pfoff = (s + 1) * KC + (g - 2) * 16; }
            else                       { havePf = false; }
            if (havePf) {
                p0 = *(const float4*)(a0p + pfoff);
                p1 = *(const float4*)(a1p + pfoff);
            }

            // B fragments from smem: one LDS.128 each, conflict-free
            const uint4* bp = buf + g * 256 + qr * 4 + j;
            uint4 bf[8];
#pragma unroll
            for (int t = 0; t < 8; t++) bf[t] = bp[t * 32];

            uint32_t aH[4], aM[4];
            cvt_split_pair(cur0.x, cur0.y, aH[0], aM[0]);   // slot 2j,   row qr
            cvt_split_pair(cur1.x, cur1.y, aH[1], aM[1]);   // slot 2j,   row qr+8
            cvt_split_pair(cur0.z, cur0.w, aH[2], aM[2]);   // slot 2j+8, row qr
            cvt_split_pair(cur1.z, cur1.w, aH[3], aM[3]);   // slot 2j+8, row qr+8

#pragma unroll
            for (int t = 0; t < 8; t++) MMA(acc[t], aH, bf[t].x, bf[t].y);
#pragma unroll
            for (int t = 0; t < 8; t++) MMA(acc[t], aM, bf[t].x, bf[t].y);
#pragma unroll
            for (int t = 0; t < 8; t++) MMA(acc[t], aH, bf[t].z, bf[t].w);

            cur0 = nx0; cur1 = nx1;
            if (havePf) { nx0 = p0; nx1 = p1; }
        }

        // store next slab into the other buffer; one barrier per stage
        if (s + 1 < NSTAGE) {
            uint4* nb = sbuf[(s + 1) & 1];
#pragma unroll
            for (int p = 0; p < 8; p++) nb[tid + p * 128] = wstage[p];
            __syncthreads();
        }
    }

    // ---- epilogue: per-row top-2 + softmax, register-only + shfl merge ----
#pragma unroll
    for (int half = 0; half < 2; half++) {
        float m1 = -3.4e38f, m2 = -3.4e38f;
        int i1 = 0, i2 = 0;
#pragma unroll
        for (int t = 0; t < 8; t++) {
#pragma unroll
            for (int c = 0; c < 2; c++) {
                float v = acc[t][half * 2 + c];
                int e = 8 * t + 2 * j + c;
                if (v > m1) { m2 = m1; i2 = i1; m1 = v; i1 = e; }
                else if (v > m2) { m2 = v; i2 = e; }
            }
        }
#pragma unroll
        for (int off = 1; off <= 2; off <<= 1) {
            float om1 = __shfl_xor_sync(0xffffffffu, m1, off);
            float om2 = __shfl_xor_sync(0xffffffffu, m2, off);
            int   oi1 = __shfl_xor_sync(0xffffffffu, i1, off);
            int   oi2 = __shfl_xor_sync(0xffffffffu, i2, off);
            if (om1 > m1) {
                float nm2 = (om2 > m1) ? om2 : m1;
                int   ni2 = (om2 > m1) ? oi2 : i1;
                m1 = om1; i1 = oi1; m2 = nm2; i2 = ni2;
            } else if (om1 > m2) {
                m2 = om1; i2 = oi1;
            }
        }
        if (j == 0) {
            int tok = tok0 + warp * 16 + qr + half * 8;
            float ex = __expf(m2 - m1);
            float s1 = 1.0f / (1.0f + ex);
            out[2 * tok]     = s1;
            out[2 * tok + 1] = ex * s1;
            out[2 * NTOK + 2 * tok]     = (float)i1;
            out[2 * NTOK + 2 * tok + 1] = (float)i2;
        }
    }
}

extern "C" void kernel_launch(void* const* d_in, const int* in_sizes, int n_in,
                              void* d_out, int out_size)
{
    const float* hs = (const float*)d_in[0];   // (4, 4096, 4096) fp32
    const float* W  = (const float*)d_in[1];   // (64, 4096) fp32
    float* out      = (float*)d_out;           // [scores 32768][indices 32768]
    (void)in_sizes; (void)n_in; (void)out_size;

    wprep_kernel<<<256, 256>>>(W);
    topk_router_kernel<<<NTOK / TOK_CTA, NTHREADS>>>(hs, out);
}

// round 13
// speedup vs baseline: 1.6220x; 1.3473x over previous
#include <cuda_runtime.h>
#include <cstdint>

#define ND 4096
#define NE 64
#define NTOK 16384
#define TOK_CTA 64
#define NTHREADS 128
#define KC 64
#define NSTAGE (ND / KC)        // 64

// Precomputed W fragments: [s][g][n][j] -> uint4 {h01, h23, m01, m23}  (1 MB)
__device__ uint4 g_wprep[NSTAGE * 4 * NE * 4];

// round-to-nearest fp16 2-way split: h = hi + mid + q, |q| <= 2^-22|h|, unbiased.
__device__ __forceinline__ void cvt_split_pair(float h0, float h1,
                                               uint32_t& hi2, uint32_t& mid2) {
    asm("cvt.rn.f16x2.f32 %0, %1, %2;" : "=r"(hi2) : "f"(h1), "f"(h0));   // lo half = h0
    float f0, f1;
    asm("{.reg .f16 a, b;\n\t mov.b32 {a, b}, %2;\n\t"
        "cvt.f32.f16 %0, a;\n\t cvt.f32.f16 %1, b;}"
        : "=f"(f0), "=f"(f1) : "r"(hi2));
    float r0 = h0 - f0;
    float r1 = h1 - f1;
    asm("cvt.rn.f16x2.f32 %0, %1, %2;" : "=r"(mid2) : "f"(r1), "f"(r0));
}

#define MMA(c, a, b0_, b1_) \
    asm volatile("mma.sync.aligned.m16n8k16.row.col.f32.f16.f16.f32 " \
        "{%0,%1,%2,%3}, {%4,%5,%6,%7}, {%8,%9}, {%0,%1,%2,%3};" \
        : "+f"((c)[0]), "+f"((c)[1]), "+f"((c)[2]), "+f"((c)[3]) \
        : "r"((a)[0]), "r"((a)[1]), "r"((a)[2]), "r"((a)[3]), "r"(b0_), "r"(b1_))

// ---- kernel 1: one-shot W conversion into fragment layout ----
__global__ __launch_bounds__(256)
void wprep_kernel(const float* __restrict__ W)
{
    const int idx = blockIdx.x * 256 + threadIdx.x;    // 65536 total
    const int j = idx & 3;
    const int n = (idx >> 2) & 63;
    const int g = (idx >> 8) & 3;
    const int s = idx >> 10;
    const int col = s * KC + g * 16 + j * 4;
    float4 w = *(const float4*)(W + (size_t)n * ND + col);
    uint32_t h01, m01, h23, m23;
    cvt_split_pair(w.x, w.y, h01, m01);
    cvt_split_pair(w.z, w.w, h23, m23);
    g_wprep[idx] = make_uint4(h01, h23, m01, m23);
}

// ---- kernel 2: GEMM + top-2 + softmax ----
__global__ __launch_bounds__(NTHREADS, 2)
void topk_router_kernel(const float* __restrict__ hs,
                        float* __restrict__ out)
{
    __shared__ __align__(16) uint4 sbuf[2][1024];   // 16 KB per stage slab

    const int tid  = threadIdx.x;
    const int lane = tid & 31;
    const int warp = tid >> 5;
    const int j    = lane & 3;     // k-slot selector
    const int qr   = lane >> 2;    // row / n selector
    const int tok0 = blockIdx.x * TOK_CTA;

    // A: permuted-K fragment loads; global col = s*64 + 16g + 4j + {0..3}
    const float* a0p = hs + (size_t)(tok0 + warp * 16 + qr) * ND + 4 * j;
    const float* a1p = a0p + 8 * ND;

    float acc[8][4];
#pragma unroll
    for (int t = 0; t < 8; t++)
#pragma unroll
        for (int c = 0; c < 4; c++) acc[t][c] = 0.f;

    uint4 wstage[8];
    float4 acur[8], anext[8];

    // ---- prologue: W slab 0 + A stage 0, both as batched bursts ----
#pragma unroll
    for (int p = 0; p < 8; p++) wstage[p] = g_wprep[tid + p * 128];
#pragma unroll
    for (int g = 0; g < 4; g++) {
        acur[2 * g]     = *(const float4*)(a0p + g * 16);
        acur[2 * g + 1] = *(const float4*)(a1p + g * 16);
    }
#pragma unroll
    for (int p = 0; p < 8; p++) sbuf[0][tid + p * 128] = wstage[p];
    __syncthreads();

    for (int s = 0; s < NSTAGE; s++) {
        // batched prefetch of next stage: W slab + all 8 A fragments (full-stage distance)
        if (s + 1 < NSTAGE) {
            const uint4* src = g_wprep + (s + 1) * 1024;
#pragma unroll
            for (int p = 0; p < 8; p++) wstage[p] = src[tid + p * 128];
            const int ko = (s + 1) * KC;
#pragma unroll
            for (int g = 0; g < 4; g++) {
                anext[2 * g]     = *(const float4*)(a0p + ko + g * 16);
                anext[2 * g + 1] = *(const float4*)(a1p + ko + g * 16);
            }
        }

        const uint4* buf = sbuf[s & 1];

#pragma unroll
        for (int g = 0; g < 4; g++) {
            // B fragments from smem: one LDS.128 each, conflict-free
            const uint4* bp = buf + g * 256 + qr * 4 + j;
            uint4 bf[8];
#pragma unroll
            for (int t = 0; t < 8; t++) bf[t] = bp[t * 32];

            uint32_t aH[4], aM[4];
            cvt_split_pair(acur[2 * g].x,     acur[2 * g].y,     aH[0], aM[0]); // slot 2j,   row qr
            cvt_split_pair(acur[2 * g + 1].x, acur[2 * g + 1].y, aH[1], aM[1]); // slot 2j,   row qr+8
            cvt_split_pair(acur[2 * g].z,     acur[2 * g].w,     aH[2], aM[2]); // slot 2j+8, row qr
            cvt_split_pair(acur[2 * g + 1].z, acur[2 * g + 1].w, aH[3], aM[3]); // slot 2j+8, row qr+8

#pragma unroll
            for (int t = 0; t < 8; t++) MMA(acc[t], aH, bf[t].x, bf[t].y);
#pragma unroll
            for (int t = 0; t < 8; t++) MMA(acc[t], aM, bf[t].x, bf[t].y);
#pragma unroll
            for (int t = 0; t < 8; t++) MMA(acc[t], aH, bf[t].z, bf[t].w);
        }

        // rotate prefetched data in; one barrier per stage
        if (s + 1 < NSTAGE) {
            uint4* nb = sbuf[(s + 1) & 1];
#pragma unroll
            for (int p = 0; p < 8; p++) nb[tid + p * 128] = wstage[p];
#pragma unroll
            for (int p = 0; p < 8; p++) acur[p] = anext[p];
            __syncthreads();
        }
    }

    // ---- epilogue: per-row top-2 + softmax, register-only + shfl merge ----
#pragma unroll
    for (int half = 0; half < 2; half++) {
        float m1 = -3.4e38f, m2 = -3.4e38f;
        int i1 = 0, i2 = 0;
#pragma unroll
        for (int t = 0; t < 8; t++) {
#pragma unroll
            for (int c = 0; c < 2; c++) {
                float v = acc[t][half * 2 + c];
                int e = 8 * t + 2 * j + c;
                if (v > m1) { m2 = m1; i2 = i1; m1 = v; i1 = e; }
                else if (v > m2) { m2 = v; i2 = e; }
            }
        }
#pragma unroll
        for (int off = 1; off <= 2; off <<= 1) {
            float om1 = __shfl_xor_sync(0xffffffffu, m1, off);
            float om2 = __shfl_xor_sync(0xffffffffu, m2, off);
            int   oi1 = __shfl_xor_sync(0xffffffffu, i1, off);
            int   oi2 = __shfl_xor_sync(0xffffffffu, i2, off);
            if (om1 > m1) {
                float nm2 = (om2 > m1) ? om2 : m1;
                int   ni2 = (om2 > m1) ? oi2 : i1;
                m1 = om1; i1 = oi1; m2 = nm2; i2 = ni2;
            } else if (om1 > m2) {
                m2 = om1; i2 = oi1;
            }
        }
        if (j == 0) {
            int tok = tok0 + warp * 16 + qr + half * 8;
            float ex = __expf(m2 - m1);
            float s1 = 1.0f / (1.0f + ex);
            out[2 * tok]     = s1;
            out[2 * tok + 1] = ex * s1;
            out[2 * NTOK + 2 * tok]     = (float)i1;
            out[2 * NTOK + 2 * tok + 1] = (float)i2;
        }
    }
}

extern "C" void kernel_launch(void* const* d_in, const int* in_sizes, int n_in,
                              void* d_out, int out_size)
{
    const float* hs = (const float*)d_in[0];   // (4, 4096, 4096) fp32
    const float* W  = (const float*)d_in[1];   // (64, 4096) fp32
    float* out      = (float*)d_out;           // [scores 32768][indices 32768]
    (void)in_sizes; (void)n_in; (void)out_size;

    wprep_kernel<<<256, 256>>>(W);
    topk_router_kernel<<<NTOK / TOK_CTA, NTHREADS>>>(hs, out);
}